// round 14
// baseline (speedup 1.0000x reference)
#include <cuda_runtime.h>
#include <cuda_fp16.h>
#include <math.h>
#include <stdint.h>

#define N_TOK 16384
#define DIM   1024
#define NEXP  8
#define HID   2048
#define NK    (N_TOK * 2)
#define NPERS 304          // persistent CTAs: 152 SMs x 2
#define NT1   16           // HID / BN
#define NT2   8            // DIM / BN
#define T0CVT 64           // W2-convert queue items
#define T3CMB 128          // combine queue items (128 tokens each)

// ---------------- scratch (no allocations allowed) -----------------------------
__device__ int    g_top_idx[NK];
__device__ float  g_top_w[NK];
__device__ int    g_cnt[NEXP];
__device__ int    g_cnt2[NEXP];
__device__ int    g_off[NEXP + 1];
__device__ int    g_tile_off[NEXP + 1];
__device__ int    g_wq[2];
__device__ int    g_dep[320];             // per-m-tile GEMM1 completion count
__device__ int    g_cW1, g_cW2, g_g2done, g_exit;
__device__ int    g_tok[NK];
__device__ int    g_pos[NK];
__device__ __half g_xh[(size_t)N_TOK * DIM];
__device__ __half g_w1h[(size_t)NEXP * DIM * HID];
__device__ __half g_w2h[(size_t)NEXP * HID * DIM];
__device__ __half g_h[(size_t)NK * HID];
__device__ __half g_y[(size_t)NK * DIM];

// ---------------- PTX helpers --------------------------------------------------
__device__ __forceinline__ uint32_t smem_u32(const void* p) {
    uint32_t a;
    asm("{ .reg .u64 t; cvta.to.shared.u64 t, %1; cvt.u32.u64 %0, t; }" : "=r"(a) : "l"(p));
    return a;
}
__device__ __forceinline__ void cp16(uint32_t d, const void* s) {
    asm volatile("cp.async.cg.shared.global [%0], [%1], 16;" :: "r"(d), "l"(s));
}
#define CP_COMMIT() asm volatile("cp.async.commit_group;" ::: "memory")
#define CP_WAIT2()  asm volatile("cp.async.wait_group 2;" ::: "memory")

__device__ __forceinline__ void ldsm4(uint32_t* r, uint32_t a) {
    asm volatile("ldmatrix.sync.aligned.m8n8.x4.shared.b16 {%0,%1,%2,%3}, [%4];"
                 : "=r"(r[0]), "=r"(r[1]), "=r"(r[2]), "=r"(r[3]) : "r"(a));
}
__device__ __forceinline__ void ldsm4t(uint32_t* r, uint32_t a) {
    asm volatile("ldmatrix.sync.aligned.m8n8.x4.trans.shared.b16 {%0,%1,%2,%3}, [%4];"
                 : "=r"(r[0]), "=r"(r[1]), "=r"(r[2]), "=r"(r[3]) : "r"(a));
}
__device__ __forceinline__ void mma16816(float* c, const uint32_t* a, const uint32_t* b) {
    asm volatile("mma.sync.aligned.m16n8k16.row.col.f32.f16.f16.f32 "
                 "{%0,%1,%2,%3}, {%4,%5,%6,%7}, {%8,%9}, {%0,%1,%2,%3};"
                 : "+f"(c[0]), "+f"(c[1]), "+f"(c[2]), "+f"(c[3])
                 : "r"(a[0]), "r"(a[1]), "r"(a[2]), "r"(a[3]), "r"(b[0]), "r"(b[1]));
}
__device__ __forceinline__ float gelu_exact(float v) {
    return 0.5f * v * (1.0f + erff(v * 0.70710678118654752f));
}
__device__ __forceinline__ void cvt_range(const float* __restrict__ s,
                                          __half* __restrict__ d,
                                          int lo, int hi, int tid) {
    for (int i = lo + tid; i < hi; i += 256) {
        float4 v = ((const float4*)s)[i];
        __half2 h0 = __floats2half2_rn(v.x, v.y);
        __half2 h1 = __floats2half2_rn(v.z, v.w);
        ((uint2*)d)[i] = make_uint2(*(uint32_t*)&h0, *(uint32_t*)&h1);
    }
}

// ---------------- fused x-convert + gating + expert counts ---------------------
__global__ void gatecvt_kernel(const float* __restrict__ x,
                               const float* __restrict__ Wg,
                               const float* __restrict__ bg) {
    __shared__ float sWg[NEXP][DIM];
    int tid = threadIdx.x, wid = tid >> 5, lane = tid & 31;
    for (int i = tid; i < DIM * NEXP / 4; i += 256) {
        int d = i >> 1, half4 = i & 1;
        float4 v = ((const float4*)(Wg + (size_t)d * NEXP))[half4];
        sWg[half4 * 4 + 0][d] = v.x; sWg[half4 * 4 + 1][d] = v.y;
        sWg[half4 * 4 + 2][d] = v.z; sWg[half4 * 4 + 3][d] = v.w;
    }
    __syncthreads();

    int tok = blockIdx.x * 8 + wid;
    const float* xr = x + (size_t)tok * DIM;
    __half* xo = g_xh + (size_t)tok * DIM;
    float acc[NEXP];
#pragma unroll
    for (int e = 0; e < NEXP; e++) acc[e] = 0.f;
#pragma unroll
    for (int it = 0; it < 8; it++) {
        int d = it * 128 + lane * 4;
        float4 xv = *(const float4*)(xr + d);
        __half2 h0 = __floats2half2_rn(xv.x, xv.y);
        __half2 h1 = __floats2half2_rn(xv.z, xv.w);
        *(uint2*)(xo + d) = make_uint2(*(uint32_t*)&h0, *(uint32_t*)&h1);
#pragma unroll
        for (int e = 0; e < NEXP; e++) {
            float4 wv = *(const float4*)&sWg[e][d];
            acc[e] += xv.x * wv.x + xv.y * wv.y + xv.z * wv.z + xv.w * wv.w;
        }
    }
#pragma unroll
    for (int e = 0; e < NEXP; e++)
#pragma unroll
        for (int s = 16; s > 0; s >>= 1)
            acc[e] += __shfl_xor_sync(0xffffffffu, acc[e], s);
    if (lane == 0) {
        float l[NEXP];
#pragma unroll
        for (int e = 0; e < NEXP; e++) l[e] = acc[e] + bg[e];
        int i0 = 0;
#pragma unroll
        for (int e = 1; e < NEXP; e++) if (l[e] > l[i0]) i0 = e;
        int i1 = (i0 == 0) ? 1 : 0;
#pragma unroll
        for (int e = 0; e < NEXP; e++) {
            if (e == i0) continue;
            if (l[e] > l[i1]) i1 = e;
        }
        float w0 = 1.f / (1.f + expf(l[i1] - l[i0]));
        g_top_idx[2 * tok]     = i0;
        g_top_idx[2 * tok + 1] = i1;
        g_top_w[2 * tok]       = w0;
        g_top_w[2 * tok + 1]   = 1.f - w0;
        atomicAdd(&g_cnt[i0], 1);
        atomicAdd(&g_cnt[i1], 1);
    }
}

// ---------------- routing ------------------------------------------------------
__global__ void route_kernel() {
    __shared__ int soff[NEXP];
    int tid = threadIdx.x;
    if (tid == 0) {
        int run = 0;
#pragma unroll
        for (int e = 0; e < NEXP; e++) { soff[e] = run; run += g_cnt[e]; }
    }
    __syncthreads();
    int i = blockIdx.x * blockDim.x + tid;
    if (i < NK) {
        int e = g_top_idx[i];
        int p = soff[e] + atomicAdd(&g_cnt2[e], 1);
        g_tok[p] = i >> 1;
        g_pos[i] = p;
    }
    if (blockIdx.x == 0 && tid == 0) {
        int run = 0, trun = 0;
#pragma unroll
        for (int e = 0; e < NEXP; e++) {
            g_off[e] = run; g_tile_off[e] = trun;
            trun += (g_cnt[e] + 127) >> 7;
            run += g_cnt[e];
        }
        g_off[NEXP] = run; g_tile_off[NEXP] = trun;
    }
}

// ---------------- GEMM tile body (R5-proven config) ----------------------------
#define BM 128
#define BN 128
#define BK 32
#define NST 4
#define A_PITCH 80
#define B_PITCH 272
#define STG_A   (BM * A_PITCH)               // 10240
#define STG_B   (BK * B_PITCH)               // 8704
#define STG_SZ  (STG_A + STG_B)              // 18944
#define OFF_BIAS (STG_SZ * NST)              // 75776
#define OFF_SRC  (OFF_BIAS + BN * 4)         // 76288
#define SMEM_BYTES (OFF_SRC + BM * 4)        // 76800
#define EP_PITCH 272

template <int KDIM, int NCOLS, bool GATHER, bool DOGELU>
__device__ __forceinline__ void gemm_tile(
    char* smem, uint32_t sb, int tid, int wm, int wn, int g, int t,
    const uint32_t* aAddr, const uint32_t (*bAddr)[4],
    const __half* __restrict__ Abase, const __half* __restrict__ Bbase,
    const float* __restrict__ biasbase, __half* __restrict__ Cout,
    int e, int moff, int M, int rows0, int n0) {
    int*   sSrc  = (int*)(smem + OFF_SRC);
    float* sBias = (float*)(smem + OFF_BIAS);
    const __half* Bexp = Bbase + (size_t)e * KDIM * NCOLS;

    if (tid < BM) {
        int s = rows0 + tid; if (s >= M) s = M - 1;
        sSrc[tid] = GATHER ? g_tok[moff + s] : (moff + s);
    }
    if (tid < BN / 4)
        ((float4*)sBias)[tid] =
            ((const float4*)(biasbase + (size_t)e * NCOLS + n0))[tid];
    __syncthreads();

    const __half* aRow[2];
    uint32_t aDst[2];
#pragma unroll
    for (int i = 0; i < 2; i++) {
        int idx = tid + i * 256;
        int r = idx >> 2, c = idx & 3;
        aRow[i] = Abase + (size_t)sSrc[r] * KDIM + c * 8;
        aDst[i] = (uint32_t)(r * A_PITCH + c * 16);
    }
    const int kb0 = tid >> 4, nc0 = tid & 15;
    const __half* bRow0 = Bexp + (size_t)kb0 * NCOLS + n0 + nc0 * 8;
    const __half* bRow1 = Bexp + (size_t)(kb0 + 16) * NCOLS + n0 + nc0 * 8;
    const uint32_t bDst0 = (uint32_t)(STG_A + kb0 * B_PITCH + nc0 * 16);
    const uint32_t bDst1 = bDst0 + 16 * B_PITCH;

    auto fill = [&](int kc) {
        int s = kc & (NST - 1);
        uint32_t base = sb + s * STG_SZ;
        cp16(base + aDst[0], aRow[0] + kc * BK);
        cp16(base + aDst[1], aRow[1] + kc * BK);
        cp16(base + bDst0, bRow0 + (size_t)kc * BK * NCOLS);
        cp16(base + bDst1, bRow1 + (size_t)kc * BK * NCOLS);
    };

    float acc[2][8][4];
#pragma unroll
    for (int mi = 0; mi < 2; mi++)
#pragma unroll
        for (int ni = 0; ni < 8; ni++)
#pragma unroll
            for (int q = 0; q < 4; q++) acc[mi][ni][q] = 0.f;

    const int NC = KDIM / BK;
    fill(0); CP_COMMIT();
    fill(1); CP_COMMIT();
    fill(2); CP_COMMIT();

    for (int kc = 0; kc < NC; kc++) {
        int s = kc & (NST - 1);
        uint32_t base = sb + s * STG_SZ;
        CP_WAIT2();
        __syncthreads();
#pragma unroll
        for (int kk = 0; kk < 2; kk++) {
            uint32_t af[2][4], bf[8][2];
#pragma unroll
            for (int mi = 0; mi < 2; mi++)
                ldsm4(af[mi], base + aAddr[mi] + kk * 32);
#pragma unroll
            for (int p = 0; p < 4; p++) {
                uint32_t r4[4];
                ldsm4t(r4, base + bAddr[kk][p]);
                bf[2 * p][0]     = r4[0]; bf[2 * p][1]     = r4[1];
                bf[2 * p + 1][0] = r4[2]; bf[2 * p + 1][1] = r4[3];
            }
#pragma unroll
            for (int mi = 0; mi < 2; mi++)
#pragma unroll
                for (int ni = 0; ni < 8; ni++)
                    mma16816(acc[mi][ni], af[mi], bf[ni]);
        }
        if (kc + 3 < NC) fill(kc + 3);
        CP_COMMIT();
    }
    __syncthreads();

    char* ep = smem;
#pragma unroll
    for (int mi = 0; mi < 2; mi++)
#pragma unroll
        for (int ni = 0; ni < 8; ni++) {
            int col = wn * 64 + ni * 8 + 2 * t;
            float bv0 = sBias[col], bv1 = sBias[col + 1];
            int rlo = wm * 32 + mi * 16 + g;
            float v0 = acc[mi][ni][0] + bv0;
            float v1 = acc[mi][ni][1] + bv1;
            float v2 = acc[mi][ni][2] + bv0;
            float v3 = acc[mi][ni][3] + bv1;
            if (DOGELU) {
                v0 = gelu_exact(v0); v1 = gelu_exact(v1);
                v2 = gelu_exact(v2); v3 = gelu_exact(v3);
            }
            __half2 hlo = __floats2half2_rn(v0, v1);
            __half2 hhi = __floats2half2_rn(v2, v3);
            *(__half2*)(ep + rlo * EP_PITCH + col * 2) = hlo;
            *(__half2*)(ep + (rlo + 8) * EP_PITCH + col * 2) = hhi;
        }
    __syncthreads();
#pragma unroll
    for (int it = 0; it < 8; it++) {
        int id = it * 256 + tid;
        int r = id >> 4, c = id & 15;
        if (rows0 + r < M) {
            uint4 v = *(uint4*)(ep + r * EP_PITCH + c * 16);
            *(uint4*)(Cout + (size_t)(moff + rows0 + r) * NCOLS + n0 + c * 8) = v;
        }
    }
}

// ---------------- mega persistent kernel: cvt + GEMM1 + GEMM2 + combine --------
// Inline phase: every CTA converts its W1 slice, bumps cW1.
// Queue: [0,T0) W2-cvt | [T0,T0+T1) GEMM1 | [..+T2) GEMM2 | [..+T3) combine.
// Gates: GEMM1 <- cW1==NPERS; GEMM2 <- cW2==T0 && dep[gm]==NT1;
//        combine <- g2done==T2.  Last-exiting CTA resets all state.
__global__ __launch_bounds__(256, 2) void mega_kernel(
    const float* __restrict__ x, const float* __restrict__ W1,
    const float* __restrict__ W2,
    const float* __restrict__ b1, const float* __restrict__ b2,
    float* __restrict__ out) {
    extern __shared__ __align__(128) char smem[];
    __shared__ int sW;
    __shared__ int sTOF[NEXP + 1];
    const uint32_t sb = smem_u32(smem);
    const int tid  = threadIdx.x;
    const int wid  = tid >> 5, lane = tid & 31;
    const int wm = wid >> 1, wn = wid & 1;
    const int g = lane >> 2, t = lane & 3;

    __half* xh  = g_xh;
    __half* w1h = g_w1h;
    __half* w2h = g_w2h;
    __half* hh  = g_h;
    __half* yh  = g_y;

    if (tid <= NEXP) sTOF[tid] = g_tile_off[tid];

    // inline W1 convert: per-CTA contiguous slice
    {
        const int n4 = NEXP * DIM * HID / 4;                 // 4194304
        const int chunk = (n4 + NPERS - 1) / NPERS;
        int lo = blockIdx.x * chunk;
        int hi = lo + chunk; if (hi > n4) hi = n4;
        cvt_range(W1, w1h, lo, hi, tid);
        __syncthreads();
        if (tid == 0) { __threadfence(); atomicAdd(&g_cW1, 1); }
    }

    // LDSM lane addresses (tile-invariant, proven mapping)
    const int lr = lane & 15, ls = lane >> 4;
    uint32_t aAddr[2], bAddr[2][4];
#pragma unroll
    for (int mi = 0; mi < 2; mi++)
        aAddr[mi] = (uint32_t)((wm * 32 + mi * 16 + lr) * A_PITCH + ls * 16);
#pragma unroll
    for (int kk = 0; kk < 2; kk++)
#pragma unroll
        for (int p = 0; p < 4; p++)
            bAddr[kk][p] = (uint32_t)(STG_A + (kk * 16 + lr) * B_PITCH +
                                      (wn * 8 + p * 2 + ls) * 16);

    bool w1ready = false;
    while (true) {
        if (tid == 0) sW = atomicAdd(&g_wq[0], 1);
        __syncthreads();
        const int w = sW;
        const int tileTot = sTOF[NEXP];
        const int T1 = tileTot * NT1;
        const int T2 = tileTot * NT2;
        if (w >= T0CVT + T1 + T2 + T3CMB) break;

        if (w < T0CVT) {
            // W2 convert item: 1/T0CVT contiguous slice
            const int n4 = NEXP * HID * DIM / 4;             // 4194304
            const int chunk = n4 / T0CVT;                    // 65536
            cvt_range(W2, w2h, w * chunk, (w + 1) * chunk, tid);
            __syncthreads();
            if (tid == 0) { __threadfence(); atomicAdd(&g_cW2, 1); }
        } else if (w < T0CVT + T1) {
            const int w1 = w - T0CVT;
            const int gm = w1 / NT1, nt = w1 % NT1;
            int e = 0;
#pragma unroll
            for (int k = 1; k < NEXP; k++) if (gm >= sTOF[k]) e = k;
            if (!w1ready) {
                if (tid == 0) {
                    while (atomicAdd(&g_cW1, 0) < NPERS) __nanosleep(100);
                }
                __syncthreads();
                w1ready = true;
            }
            gemm_tile<DIM, HID, true, true>(smem, sb, tid, wm, wn, g, t,
                aAddr, bAddr, xh, w1h, b1, hh,
                e, g_off[e], g_off[e + 1] - g_off[e], (gm - sTOF[e]) * BM, nt * BN);
            __threadfence();
            __syncthreads();
            if (tid == 0) atomicAdd(&g_dep[gm], 1);
        } else if (w < T0CVT + T1 + T2) {
            const int w2 = w - T0CVT - T1;
            const int gm = w2 / NT2, nt = w2 % NT2;
            int e = 0;
#pragma unroll
            for (int k = 1; k < NEXP; k++) if (gm >= sTOF[k]) e = k;
            if (tid == 0) {
                while (atomicAdd(&g_cW2, 0) < T0CVT) __nanosleep(100);
                while (atomicAdd(&g_dep[gm], 0) < NT1) __nanosleep(200);
            }
            __syncthreads();
            gemm_tile<HID, DIM, false, false>(smem, sb, tid, wm, wn, g, t,
                aAddr, bAddr, hh, w2h, b2, yh,
                e, g_off[e], g_off[e + 1] - g_off[e], (gm - sTOF[e]) * BM, nt * BN);
            __threadfence();
            __syncthreads();
            if (tid == 0) atomicAdd(&g_g2done, 1);
        } else {
            // combine item: 128 tokens, residual + weighted expert outputs
            if (tid == 0) {
                while (atomicAdd(&g_g2done, 0) < T2) __nanosleep(200);
            }
            __syncthreads();
            const int tok0 = (w - T0CVT - T1 - T2) * 128;
#pragma unroll
            for (int it = 0; it < 64; it++) {
                int slot = it * 256 + tid;
                int n = tok0 + (slot >> 7);
                int c = (slot & 127) * 8;
                int p0 = g_pos[2 * n], p1 = g_pos[2 * n + 1];
                float wg0 = g_top_w[2 * n], wg1 = g_top_w[2 * n + 1];
                const float* xr = x + (size_t)n * DIM + c;
                float4 x0 = ((const float4*)xr)[0];
                float4 x1 = ((const float4*)xr)[1];
                uint4 ya = *(const uint4*)(yh + (size_t)p0 * DIM + c);
                uint4 yb = *(const uint4*)(yh + (size_t)p1 * DIM + c);
                float2 a0 = __half22float2(*(__half2*)&ya.x), a1 = __half22float2(*(__half2*)&ya.y);
                float2 a2 = __half22float2(*(__half2*)&ya.z), a3 = __half22float2(*(__half2*)&ya.w);
                float2 b0 = __half22float2(*(__half2*)&yb.x), b1v = __half22float2(*(__half2*)&yb.y);
                float2 b2v = __half22float2(*(__half2*)&yb.z), b3 = __half22float2(*(__half2*)&yb.w);
                float4 o0, o1;
                o0.x = x0.x + wg0 * a0.x + wg1 * b0.x;
                o0.y = x0.y + wg0 * a0.y + wg1 * b0.y;
                o0.z = x0.z + wg0 * a1.x + wg1 * b1v.x;
                o0.w = x0.w + wg0 * a1.y + wg1 * b1v.y;
                o1.x = x1.x + wg0 * a2.x + wg1 * b2v.x;
                o1.y = x1.y + wg0 * a2.y + wg1 * b2v.y;
                o1.z = x1.z + wg0 * a3.x + wg1 * b3.x;
                o1.w = x1.w + wg0 * a3.y + wg1 * b3.y;
                float* orow = out + (size_t)n * DIM + c;
                ((float4*)orow)[0] = o0;
                ((float4*)orow)[1] = o1;
            }
        }
    }

    // exit: last CTA resets all inter-launch state for graph replay
    if (tid == 0) {
        int old = atomicAdd(&g_exit, 1);
        if (old == NPERS - 1) {
            g_wq[0] = 0; g_wq[1] = 0;
            g_cW1 = 0; g_cW2 = 0; g_g2done = 0; g_exit = 0;
#pragma unroll
            for (int e = 0; e < NEXP; e++) { g_cnt[e] = 0; g_cnt2[e] = 0; }
            for (int i = 0; i < 320; i++) g_dep[i] = 0;
            __threadfence();
        }
    }
}

// ---------------- launch -------------------------------------------------------
extern "C" void kernel_launch(void* const* d_in, const int* in_sizes, int n_in,
                              void* d_out, int out_size) {
    const float* x  = (const float*)d_in[0];
    const float* Wg = (const float*)d_in[1];
    const float* bg = (const float*)d_in[2];
    const float* W1 = (const float*)d_in[3];
    const float* b1 = (const float*)d_in[4];
    const float* W2 = (const float*)d_in[5];
    const float* b2 = (const float*)d_in[6];
    float* out = (float*)d_out;

    cudaFuncSetAttribute(mega_kernel,
                         cudaFuncAttributeMaxDynamicSharedMemorySize, SMEM_BYTES);

    gatecvt_kernel<<<N_TOK / 8, 256>>>(x, Wg, bg);          // 0
    route_kernel<<<NK / 256, 256>>>();                       // 1
    mega_kernel<<<NPERS, 256, SMEM_BYTES>>>(x, W1, W2,       // 2
                                            b1, b2, out);
}

// round 15
// speedup vs baseline: 1.0671x; 1.0671x over previous
#include <cuda_runtime.h>
#include <cuda_fp16.h>
#include <math.h>
#include <stdint.h>

#define N_TOK 16384
#define DIM   1024
#define NEXP  8
#define HID   2048
#define NK    (N_TOK * 2)
#define NPERS 304          // persistent CTAs: 152 SMs x 2
#define NT1   16           // HID / BN
#define NT2   8            // DIM / BN

// ---------------- scratch (no allocations allowed) -----------------------------
__device__ int    g_top_idx[NK];
__device__ float  g_top_w[NK];
__device__ int    g_cnt[NEXP];
__device__ int    g_cnt2[NEXP];
__device__ int    g_off[NEXP + 1];
__device__ int    g_tile_off[NEXP + 1];
__device__ int    g_wq[2];
__device__ int    g_dep[320];             // per-m-tile GEMM1 completion count
__device__ int    g_tok[NK];
__device__ int    g_pos[NK];
__device__ __half g_xh[(size_t)N_TOK * DIM];
__device__ __half g_w1h[(size_t)NEXP * DIM * HID];
__device__ __half g_w2h[(size_t)NEXP * HID * DIM];
__device__ __half g_h[(size_t)NK * HID];
__device__ __half g_y[(size_t)NK * DIM];

// ---------------- PTX helpers --------------------------------------------------
__device__ __forceinline__ uint32_t smem_u32(const void* p) {
    uint32_t a;
    asm("{ .reg .u64 t; cvta.to.shared.u64 t, %1; cvt.u32.u64 %0, t; }" : "=r"(a) : "l"(p));
    return a;
}
__device__ __forceinline__ void cp16(uint32_t d, const void* s) {
    asm volatile("cp.async.cg.shared.global [%0], [%1], 16;" :: "r"(d), "l"(s));
}
#define CP_COMMIT() asm volatile("cp.async.commit_group;" ::: "memory")
#define CP_WAIT2()  asm volatile("cp.async.wait_group 2;" ::: "memory")

__device__ __forceinline__ void ldsm4(uint32_t* r, uint32_t a) {
    asm volatile("ldmatrix.sync.aligned.m8n8.x4.shared.b16 {%0,%1,%2,%3}, [%4];"
                 : "=r"(r[0]), "=r"(r[1]), "=r"(r[2]), "=r"(r[3]) : "r"(a));
}
__device__ __forceinline__ void ldsm4t(uint32_t* r, uint32_t a) {
    asm volatile("ldmatrix.sync.aligned.m8n8.x4.trans.shared.b16 {%0,%1,%2,%3}, [%4];"
                 : "=r"(r[0]), "=r"(r[1]), "=r"(r[2]), "=r"(r[3]) : "r"(a));
}
__device__ __forceinline__ void mma16816(float* c, const uint32_t* a, const uint32_t* b) {
    asm volatile("mma.sync.aligned.m16n8k16.row.col.f32.f16.f16.f32 "
                 "{%0,%1,%2,%3}, {%4,%5,%6,%7}, {%8,%9}, {%0,%1,%2,%3};"
                 : "+f"(c[0]), "+f"(c[1]), "+f"(c[2]), "+f"(c[3])
                 : "r"(a[0]), "r"(a[1]), "r"(a[2]), "r"(a[3]), "r"(b[0]), "r"(b[1]));
}
__device__ __forceinline__ float gelu_exact(float v) {
    return 0.5f * v * (1.0f + erff(v * 0.70710678118654752f));
}

// ---------------- merged fp32 -> fp16 convert (W1 + W2) ------------------------
__global__ void cvt2_kernel(const float* __restrict__ s1, __half* __restrict__ d1, int n1,
                            const float* __restrict__ s2, __half* __restrict__ d2, int n2) {
    int i = blockIdx.x * blockDim.x + threadIdx.x;
    int stride = gridDim.x * blockDim.x;
    for (; i < n1 + n2; i += stride) {
        const float* s; __half* d; int j;
        if (i < n1) { s = s1; d = d1; j = i; }
        else        { s = s2; d = d2; j = i - n1; }
        float4 v = ((const float4*)s)[j];
        __half2 h0 = __floats2half2_rn(v.x, v.y);
        __half2 h1 = __floats2half2_rn(v.z, v.w);
        ((uint2*)d)[j] = make_uint2(*(uint32_t*)&h0, *(uint32_t*)&h1);
    }
}

// ---------------- fused x-convert + gating + expert counts ---------------------
// 8 warps/block, 4 tokens/warp: each sWg read feeds 4 tokens (4x L1 reduction),
// 512 blocks (4x less Wg gmem traffic).
__global__ void gatecvt_kernel(const float* __restrict__ x,
                               const float* __restrict__ Wg,
                               const float* __restrict__ bg) {
    __shared__ float sWg[NEXP][DIM];
    int tid = threadIdx.x, wid = tid >> 5, lane = tid & 31;
    for (int i = tid; i < DIM * NEXP / 4; i += 256) {
        int d = i >> 1, half4 = i & 1;
        float4 v = ((const float4*)(Wg + (size_t)d * NEXP))[half4];
        sWg[half4 * 4 + 0][d] = v.x; sWg[half4 * 4 + 1][d] = v.y;
        sWg[half4 * 4 + 2][d] = v.z; sWg[half4 * 4 + 3][d] = v.w;
    }
    __syncthreads();

    int tok0 = (blockIdx.x * 8 + wid) * 4;
    float acc[4][NEXP];
#pragma unroll
    for (int tk = 0; tk < 4; tk++)
#pragma unroll
        for (int e = 0; e < NEXP; e++) acc[tk][e] = 0.f;

#pragma unroll
    for (int it = 0; it < 8; it++) {
        int d = it * 128 + lane * 4;
        float4 xv[4];
#pragma unroll
        for (int tk = 0; tk < 4; tk++) {
            xv[tk] = *(const float4*)(x + (size_t)(tok0 + tk) * DIM + d);
            __half2 h0 = __floats2half2_rn(xv[tk].x, xv[tk].y);
            __half2 h1 = __floats2half2_rn(xv[tk].z, xv[tk].w);
            *(uint2*)(g_xh + (size_t)(tok0 + tk) * DIM + d) =
                make_uint2(*(uint32_t*)&h0, *(uint32_t*)&h1);
        }
#pragma unroll
        for (int e = 0; e < NEXP; e++) {
            float4 wv = *(const float4*)&sWg[e][d];
#pragma unroll
            for (int tk = 0; tk < 4; tk++)
                acc[tk][e] += xv[tk].x * wv.x + xv[tk].y * wv.y +
                              xv[tk].z * wv.z + xv[tk].w * wv.w;
        }
    }
#pragma unroll
    for (int tk = 0; tk < 4; tk++)
#pragma unroll
        for (int e = 0; e < NEXP; e++)
#pragma unroll
            for (int s = 16; s > 0; s >>= 1)
                acc[tk][e] += __shfl_xor_sync(0xffffffffu, acc[tk][e], s);
    // after bfly reduction every lane holds full sums; lanes 0-3 finalize 1 token
    if (lane < 4) {
        int tok = tok0 + lane;
        float l[NEXP];
#pragma unroll
        for (int e = 0; e < NEXP; e++) l[e] = acc[lane][e] + bg[e];
        int i0 = 0;
#pragma unroll
        for (int e = 1; e < NEXP; e++) if (l[e] > l[i0]) i0 = e;
        int i1 = (i0 == 0) ? 1 : 0;
#pragma unroll
        for (int e = 0; e < NEXP; e++) {
            if (e == i0) continue;
            if (l[e] > l[i1]) i1 = e;
        }
        float w0 = 1.f / (1.f + expf(l[i1] - l[i0]));
        g_top_idx[2 * tok]     = i0;
        g_top_idx[2 * tok + 1] = i1;
        g_top_w[2 * tok]       = w0;
        g_top_w[2 * tok + 1]   = 1.f - w0;
        atomicAdd(&g_cnt[i0], 1);
        atomicAdd(&g_cnt[i1], 1);
    }
}

// ---------------- routing ------------------------------------------------------
__global__ void route_kernel() {
    __shared__ int soff[NEXP];
    int tid = threadIdx.x;
    if (tid == 0) {
        int run = 0;
#pragma unroll
        for (int e = 0; e < NEXP; e++) { soff[e] = run; run += g_cnt[e]; }
    }
    __syncthreads();
    int i = blockIdx.x * blockDim.x + tid;
    if (i < NK) {
        int e = g_top_idx[i];
        int p = soff[e] + atomicAdd(&g_cnt2[e], 1);
        g_tok[p] = i >> 1;
        g_pos[i] = p;
    }
    if (blockIdx.x == 0 && tid == 0) {
        int run = 0, trun = 0;
#pragma unroll
        for (int e = 0; e < NEXP; e++) {
            g_off[e] = run; g_tile_off[e] = trun;
            trun += (g_cnt[e] + 127) >> 7;
            run += g_cnt[e];
        }
        g_off[NEXP] = run; g_tile_off[NEXP] = trun;
    }
}

// ---------------- GEMM tile body (R5-proven config) ----------------------------
#define BM 128
#define BN 128
#define BK 32
#define NST 4
#define A_PITCH 80
#define B_PITCH 272
#define STG_A   (BM * A_PITCH)               // 10240
#define STG_B   (BK * B_PITCH)               // 8704
#define STG_SZ  (STG_A + STG_B)              // 18944
#define OFF_BIAS (STG_SZ * NST)              // 75776
#define OFF_SRC  (OFF_BIAS + BN * 4)         // 76288
#define SMEM_BYTES (OFF_SRC + BM * 4)        // 76800
#define EP_PITCH 272

template <int KDIM, int NCOLS, bool GATHER, bool DOGELU>
__device__ __forceinline__ void gemm_tile(
    char* smem, uint32_t sb, int tid, int wm, int wn, int g, int t,
    const uint32_t* aAddr, const uint32_t (*bAddr)[4],
    const __half* __restrict__ Abase, const __half* __restrict__ Bbase,
    const float* __restrict__ biasbase, __half* __restrict__ Cout,
    int e, int moff, int M, int rows0, int n0) {
    int*   sSrc  = (int*)(smem + OFF_SRC);
    float* sBias = (float*)(smem + OFF_BIAS);
    const __half* Bexp = Bbase + (size_t)e * KDIM * NCOLS;

    if (tid < BM) {
        int s = rows0 + tid; if (s >= M) s = M - 1;
        sSrc[tid] = GATHER ? g_tok[moff + s] : (moff + s);
    }
    if (tid < BN / 4)
        ((float4*)sBias)[tid] =
            ((const float4*)(biasbase + (size_t)e * NCOLS + n0))[tid];
    __syncthreads();

    const __half* aRow[2];
    uint32_t aDst[2];
#pragma unroll
    for (int i = 0; i < 2; i++) {
        int idx = tid + i * 256;
        int r = idx >> 2, c = idx & 3;
        aRow[i] = Abase + (size_t)sSrc[r] * KDIM + c * 8;
        aDst[i] = (uint32_t)(r * A_PITCH + c * 16);
    }
    const int kb0 = tid >> 4, nc0 = tid & 15;
    const __half* bRow0 = Bexp + (size_t)kb0 * NCOLS + n0 + nc0 * 8;
    const __half* bRow1 = Bexp + (size_t)(kb0 + 16) * NCOLS + n0 + nc0 * 8;
    const uint32_t bDst0 = (uint32_t)(STG_A + kb0 * B_PITCH + nc0 * 16);
    const uint32_t bDst1 = bDst0 + 16 * B_PITCH;

    auto fill = [&](int kc) {
        int s = kc & (NST - 1);
        uint32_t base = sb + s * STG_SZ;
        cp16(base + aDst[0], aRow[0] + kc * BK);
        cp16(base + aDst[1], aRow[1] + kc * BK);
        cp16(base + bDst0, bRow0 + (size_t)kc * BK * NCOLS);
        cp16(base + bDst1, bRow1 + (size_t)kc * BK * NCOLS);
    };

    float acc[2][8][4];
#pragma unroll
    for (int mi = 0; mi < 2; mi++)
#pragma unroll
        for (int ni = 0; ni < 8; ni++)
#pragma unroll
            for (int q = 0; q < 4; q++) acc[mi][ni][q] = 0.f;

    const int NC = KDIM / BK;
    fill(0); CP_COMMIT();
    fill(1); CP_COMMIT();
    fill(2); CP_COMMIT();

    for (int kc = 0; kc < NC; kc++) {
        int s = kc & (NST - 1);
        uint32_t base = sb + s * STG_SZ;
        CP_WAIT2();
        __syncthreads();
#pragma unroll
        for (int kk = 0; kk < 2; kk++) {
            uint32_t af[2][4], bf[8][2];
#pragma unroll
            for (int mi = 0; mi < 2; mi++)
                ldsm4(af[mi], base + aAddr[mi] + kk * 32);
#pragma unroll
            for (int p = 0; p < 4; p++) {
                uint32_t r4[4];
                ldsm4t(r4, base + bAddr[kk][p]);
                bf[2 * p][0]     = r4[0]; bf[2 * p][1]     = r4[1];
                bf[2 * p + 1][0] = r4[2]; bf[2 * p + 1][1] = r4[3];
            }
#pragma unroll
            for (int mi = 0; mi < 2; mi++)
#pragma unroll
                for (int ni = 0; ni < 8; ni++)
                    mma16816(acc[mi][ni], af[mi], bf[ni]);
        }
        if (kc + 3 < NC) fill(kc + 3);
        CP_COMMIT();
    }
    __syncthreads();

    char* ep = smem;
#pragma unroll
    for (int mi = 0; mi < 2; mi++)
#pragma unroll
        for (int ni = 0; ni < 8; ni++) {
            int col = wn * 64 + ni * 8 + 2 * t;
            float bv0 = sBias[col], bv1 = sBias[col + 1];
            int rlo = wm * 32 + mi * 16 + g;
            float v0 = acc[mi][ni][0] + bv0;
            float v1 = acc[mi][ni][1] + bv1;
            float v2 = acc[mi][ni][2] + bv0;
            float v3 = acc[mi][ni][3] + bv1;
            if (DOGELU) {
                v0 = gelu_exact(v0); v1 = gelu_exact(v1);
                v2 = gelu_exact(v2); v3 = gelu_exact(v3);
            }
            __half2 hlo = __floats2half2_rn(v0, v1);
            __half2 hhi = __floats2half2_rn(v2, v3);
            *(__half2*)(ep + rlo * EP_PITCH + col * 2) = hlo;
            *(__half2*)(ep + (rlo + 8) * EP_PITCH + col * 2) = hhi;
        }
    __syncthreads();
#pragma unroll
    for (int it = 0; it < 8; it++) {
        int id = it * 256 + tid;
        int r = id >> 4, c = id & 15;
        if (rows0 + r < M) {
            uint4 v = *(uint4*)(ep + r * EP_PITCH + c * 16);
            *(uint4*)(Cout + (size_t)(moff + rows0 + r) * NCOLS + n0 + c * 8) = v;
        }
    }
}

// ---------------- fused persistent GEMM1+GEMM2 ---------------------------------
// Single queue: items [0, T1) = GEMM1 tiles (m-major), [T1, T1+T2) = GEMM2.
// GEMM1 tile completion bumps g_dep[gm]; GEMM2 tiles wait for dep==NT1.
__global__ __launch_bounds__(256, 2) void fused_gemm(
    const __half* __restrict__ xh, const __half* __restrict__ w1h,
    const float* __restrict__ b1, __half* __restrict__ hh,
    const __half* __restrict__ w2h, const float* __restrict__ b2,
    __half* __restrict__ yh) {
    extern __shared__ __align__(128) char smem[];
    __shared__ int sW;
    __shared__ int sTOF[NEXP + 1];
    const uint32_t sb = smem_u32(smem);
    const int tid  = threadIdx.x;
    const int wid  = tid >> 5, lane = tid & 31;
    const int wm = wid >> 1, wn = wid & 1;
    const int g = lane >> 2, t = lane & 3;

    if (tid <= NEXP) sTOF[tid] = g_tile_off[tid];

    const int lr = lane & 15, ls = lane >> 4;
    uint32_t aAddr[2], bAddr[2][4];
#pragma unroll
    for (int mi = 0; mi < 2; mi++)
        aAddr[mi] = (uint32_t)((wm * 32 + mi * 16 + lr) * A_PITCH + ls * 16);
#pragma unroll
    for (int kk = 0; kk < 2; kk++)
#pragma unroll
        for (int p = 0; p < 4; p++)
            bAddr[kk][p] = (uint32_t)(STG_A + (kk * 16 + lr) * B_PITCH +
                                      (wn * 8 + p * 2 + ls) * 16);

    while (true) {
        if (tid == 0) sW = atomicAdd(&g_wq[0], 1);
        __syncthreads();
        const int w = sW;
        const int tileTot = sTOF[NEXP];
        const int T1 = tileTot * NT1;
        const int T2 = tileTot * NT2;
        if (w >= T1 + T2) break;

        const bool isG1 = (w < T1);
        int gm, nt;
        if (isG1) { gm = w / NT1; nt = w % NT1; }
        else      { int w2 = w - T1; gm = w2 / NT2; nt = w2 % NT2; }
        int e = 0;
#pragma unroll
        for (int k = 1; k < NEXP; k++) if (gm >= sTOF[k]) e = k;
        const int moff  = g_off[e];
        const int M     = g_off[e + 1] - moff;
        const int rows0 = (gm - sTOF[e]) * BM;
        const int n0    = nt * BN;

        if (isG1) {
            gemm_tile<DIM, HID, true, true>(smem, sb, tid, wm, wn, g, t,
                aAddr, bAddr, xh, w1h, b1, hh, e, moff, M, rows0, n0);
            __threadfence();
            __syncthreads();
            if (tid == 0) atomicAdd(&g_dep[gm], 1);
        } else {
            if (tid == 0) {
                while (atomicAdd(&g_dep[gm], 0) < NT1) __nanosleep(200);
            }
            __syncthreads();
            gemm_tile<HID, DIM, false, false>(smem, sb, tid, wm, wn, g, t,
                aAddr, bAddr, hh, w2h, b2, yh, e, moff, M, rows0, n0);
        }
    }
}

// ---------------- combine (fp16 y) + state reset for graph replay --------------
__global__ void combine_kernel(const float* __restrict__ x, float* __restrict__ out) {
    int idx = blockIdx.x * blockDim.x + threadIdx.x;
    int n = idx >> 7;
    int c = (idx & 127) * 8;
    int p0 = g_pos[2 * n], p1 = g_pos[2 * n + 1];
    float w0 = g_top_w[2 * n], w1 = g_top_w[2 * n + 1];
    const float* xr = x + (size_t)n * DIM + c;
    float4 x0 = ((const float4*)xr)[0];
    float4 x1 = ((const float4*)xr)[1];
    uint4 ya = *(const uint4*)(g_y + (size_t)p0 * DIM + c);
    uint4 yb = *(const uint4*)(g_y + (size_t)p1 * DIM + c);
    float2 a0 = __half22float2(*(__half2*)&ya.x), a1 = __half22float2(*(__half2*)&ya.y);
    float2 a2 = __half22float2(*(__half2*)&ya.z), a3 = __half22float2(*(__half2*)&ya.w);
    float2 b0 = __half22float2(*(__half2*)&yb.x), b1 = __half22float2(*(__half2*)&yb.y);
    float2 b2 = __half22float2(*(__half2*)&yb.z), b3 = __half22float2(*(__half2*)&yb.w);
    float4 o0, o1;
    o0.x = x0.x + w0 * a0.x + w1 * b0.x;
    o0.y = x0.y + w0 * a0.y + w1 * b0.y;
    o0.z = x0.z + w0 * a1.x + w1 * b1.x;
    o0.w = x0.w + w0 * a1.y + w1 * b1.y;
    o1.x = x1.x + w0 * a2.x + w1 * b2.x;
    o1.y = x1.y + w0 * a2.y + w1 * b2.y;
    o1.z = x1.z + w0 * a3.x + w1 * b3.x;
    o1.w = x1.w + w0 * a3.y + w1 * b3.y;
    float* orow = out + (size_t)n * DIM + c;
    ((float4*)orow)[0] = o0;
    ((float4*)orow)[1] = o1;
    if (blockIdx.x == 0) {
        if (threadIdx.x < NEXP) { g_cnt[threadIdx.x] = 0; g_cnt2[threadIdx.x] = 0; }
        if (threadIdx.x < 2) g_wq[threadIdx.x] = 0;
        for (int i = threadIdx.x; i < 320; i += 256) g_dep[i] = 0;
    }
}

// ---------------- launch (single stream, R13 ordering) -------------------------
extern "C" void kernel_launch(void* const* d_in, const int* in_sizes, int n_in,
                              void* d_out, int out_size) {
    const float* x  = (const float*)d_in[0];
    const float* Wg = (const float*)d_in[1];
    const float* bg = (const float*)d_in[2];
    const float* W1 = (const float*)d_in[3];
    const float* b1 = (const float*)d_in[4];
    const float* W2 = (const float*)d_in[5];
    const float* b2 = (const float*)d_in[6];
    float* out = (float*)d_out;

    cudaFuncSetAttribute(fused_gemm,
                         cudaFuncAttributeMaxDynamicSharedMemorySize, SMEM_BYTES);

    __half *xh, *w1h, *w2h, *hh, *yh;
    cudaGetSymbolAddress((void**)&xh,  g_xh);
    cudaGetSymbolAddress((void**)&w1h, g_w1h);
    cudaGetSymbolAddress((void**)&w2h, g_w2h);
    cudaGetSymbolAddress((void**)&hh,  g_h);
    cudaGetSymbolAddress((void**)&yh,  g_y);

    gatecvt_kernel<<<N_TOK / 32, 256>>>(x, Wg, bg);                   // 0
    route_kernel<<<NK / 256, 256>>>();                                 // 1
    cvt2_kernel<<<4096, 256>>>(W1, w1h, NEXP * DIM * HID / 4,          // 2
                               W2, w2h, NEXP * HID * DIM / 4);
    fused_gemm<<<NPERS, 256, SMEM_BYTES>>>(xh, w1h, b1, hh,            // 3 (profiled)
                                           w2h, b2, yh);
    combine_kernel<<<N_TOK * 128 / 256, 256>>>(x, out);                // 4
}

// round 16
// speedup vs baseline: 1.0707x; 1.0035x over previous
#include <cuda_runtime.h>
#include <cuda_fp16.h>
#include <math.h>
#include <stdint.h>

#define N_TOK 16384
#define DIM   1024
#define NEXP  8
#define HID   2048
#define NK    (N_TOK * 2)
#define NPERS 304          // persistent CTAs: 152 SMs x 2
#define NT1   16           // HID / BN
#define NT2   8            // DIM / BN
#define GATE_BLKS 512      // gating blocks inside prep_kernel
#define CVT_BLKS  2048     // weight-cvt blocks inside prep_kernel

// ---------------- scratch (no allocations allowed) -----------------------------
__device__ int    g_top_idx[NK];
__device__ float  g_top_w[NK];
__device__ int    g_cnt[NEXP];
__device__ int    g_cnt2[NEXP];
__device__ int    g_off[NEXP + 1];
__device__ int    g_tile_off[NEXP + 1];
__device__ int    g_wq[2];
__device__ int    g_dep[320];             // per-m-tile GEMM1 completion count
__device__ int    g_tok[NK];
__device__ int    g_pos[NK];
__device__ __half g_xh[(size_t)N_TOK * DIM];
__device__ __half g_w1h[(size_t)NEXP * DIM * HID];
__device__ __half g_w2h[(size_t)NEXP * HID * DIM];
__device__ __half g_h[(size_t)NK * HID];
__device__ __half g_y[(size_t)NK * DIM];

// ---------------- PTX helpers --------------------------------------------------
__device__ __forceinline__ uint32_t smem_u32(const void* p) {
    uint32_t a;
    asm("{ .reg .u64 t; cvta.to.shared.u64 t, %1; cvt.u32.u64 %0, t; }" : "=r"(a) : "l"(p));
    return a;
}
__device__ __forceinline__ void cp16(uint32_t d, const void* s) {
    asm volatile("cp.async.cg.shared.global [%0], [%1], 16;" :: "r"(d), "l"(s));
}
#define CP_COMMIT() asm volatile("cp.async.commit_group;" ::: "memory")
#define CP_WAIT2()  asm volatile("cp.async.wait_group 2;" ::: "memory")

__device__ __forceinline__ void ldsm4(uint32_t* r, uint32_t a) {
    asm volatile("ldmatrix.sync.aligned.m8n8.x4.shared.b16 {%0,%1,%2,%3}, [%4];"
                 : "=r"(r[0]), "=r"(r[1]), "=r"(r[2]), "=r"(r[3]) : "r"(a));
}
__device__ __forceinline__ void ldsm4t(uint32_t* r, uint32_t a) {
    asm volatile("ldmatrix.sync.aligned.m8n8.x4.trans.shared.b16 {%0,%1,%2,%3}, [%4];"
                 : "=r"(r[0]), "=r"(r[1]), "=r"(r[2]), "=r"(r[3]) : "r"(a));
}
__device__ __forceinline__ void mma16816(float* c, const uint32_t* a, const uint32_t* b) {
    asm volatile("mma.sync.aligned.m16n8k16.row.col.f32.f16.f16.f32 "
                 "{%0,%1,%2,%3}, {%4,%5,%6,%7}, {%8,%9}, {%0,%1,%2,%3};"
                 : "+f"(c[0]), "+f"(c[1]), "+f"(c[2]), "+f"(c[3])
                 : "r"(a[0]), "r"(a[1]), "r"(a[2]), "r"(a[3]), "r"(b[0]), "r"(b[1]));
}
__device__ __forceinline__ float gelu_exact(float v) {
    return 0.5f * v * (1.0f + erff(v * 0.70710678118654752f));
}

// ---------------- prep: gating (blocks < GATE_BLKS) + weight cvt (rest) --------
__global__ void prep_kernel(const float* __restrict__ x,
                            const float* __restrict__ Wg,
                            const float* __restrict__ bg,
                            const float* __restrict__ W1,
                            const float* __restrict__ W2) {
    int tid = threadIdx.x;
    if (blockIdx.x >= GATE_BLKS) {
        // ---- weight convert: W1 then W2, grid-stride over both ----
        const int n1 = NEXP * DIM * HID / 4;
        const int n2 = NEXP * HID * DIM / 4;
        int i = (blockIdx.x - GATE_BLKS) * 256 + tid;
        const int stride = CVT_BLKS * 256;
        for (; i < n1 + n2; i += stride) {
            const float* s; __half* d; int j;
            if (i < n1) { s = W1; d = g_w1h; j = i; }
            else        { s = W2; d = g_w2h; j = i - n1; }
            float4 v = ((const float4*)s)[j];
            __half2 h0 = __floats2half2_rn(v.x, v.y);
            __half2 h1 = __floats2half2_rn(v.z, v.w);
            ((uint2*)d)[j] = make_uint2(*(uint32_t*)&h0, *(uint32_t*)&h1);
        }
        return;
    }

    // ---- gating: 8 warps/block, 4 tokens/warp (proven R15 body) ----
    __shared__ float sWg[NEXP][DIM];
    int wid = tid >> 5, lane = tid & 31;
    for (int i = tid; i < DIM * NEXP / 4; i += 256) {
        int d = i >> 1, half4 = i & 1;
        float4 v = ((const float4*)(Wg + (size_t)d * NEXP))[half4];
        sWg[half4 * 4 + 0][d] = v.x; sWg[half4 * 4 + 1][d] = v.y;
        sWg[half4 * 4 + 2][d] = v.z; sWg[half4 * 4 + 3][d] = v.w;
    }
    __syncthreads();

    int tok0 = (blockIdx.x * 8 + wid) * 4;
    float acc[4][NEXP];
#pragma unroll
    for (int tk = 0; tk < 4; tk++)
#pragma unroll
        for (int e = 0; e < NEXP; e++) acc[tk][e] = 0.f;

#pragma unroll
    for (int it = 0; it < 8; it++) {
        int d = it * 128 + lane * 4;
        float4 xv[4];
#pragma unroll
        for (int tk = 0; tk < 4; tk++) {
            xv[tk] = *(const float4*)(x + (size_t)(tok0 + tk) * DIM + d);
            __half2 h0 = __floats2half2_rn(xv[tk].x, xv[tk].y);
            __half2 h1 = __floats2half2_rn(xv[tk].z, xv[tk].w);
            *(uint2*)(g_xh + (size_t)(tok0 + tk) * DIM + d) =
                make_uint2(*(uint32_t*)&h0, *(uint32_t*)&h1);
        }
#pragma unroll
        for (int e = 0; e < NEXP; e++) {
            float4 wv = *(const float4*)&sWg[e][d];
#pragma unroll
            for (int tk = 0; tk < 4; tk++)
                acc[tk][e] += xv[tk].x * wv.x + xv[tk].y * wv.y +
                              xv[tk].z * wv.z + xv[tk].w * wv.w;
        }
    }
#pragma unroll
    for (int tk = 0; tk < 4; tk++)
#pragma unroll
        for (int e = 0; e < NEXP; e++)
#pragma unroll
            for (int s = 16; s > 0; s >>= 1)
                acc[tk][e] += __shfl_xor_sync(0xffffffffu, acc[tk][e], s);
    if (lane < 4) {
        int tok = tok0 + lane;
        float l[NEXP];
#pragma unroll
        for (int e = 0; e < NEXP; e++) l[e] = acc[lane][e] + bg[e];
        int i0 = 0;
#pragma unroll
        for (int e = 1; e < NEXP; e++) if (l[e] > l[i0]) i0 = e;
        int i1 = (i0 == 0) ? 1 : 0;
#pragma unroll
        for (int e = 0; e < NEXP; e++) {
            if (e == i0) continue;
            if (l[e] > l[i1]) i1 = e;
        }
        float w0 = 1.f / (1.f + expf(l[i1] - l[i0]));
        g_top_idx[2 * tok]     = i0;
        g_top_idx[2 * tok + 1] = i1;
        g_top_w[2 * tok]       = w0;
        g_top_w[2 * tok + 1]   = 1.f - w0;
        atomicAdd(&g_cnt[i0], 1);
        atomicAdd(&g_cnt[i1], 1);
    }
}

// ---------------- routing ------------------------------------------------------
__global__ void route_kernel() {
    __shared__ int soff[NEXP];
    int tid = threadIdx.x;
    if (tid == 0) {
        int run = 0;
#pragma unroll
        for (int e = 0; e < NEXP; e++) { soff[e] = run; run += g_cnt[e]; }
    }
    __syncthreads();
    int i = blockIdx.x * blockDim.x + tid;
    if (i < NK) {
        int e = g_top_idx[i];
        int p = soff[e] + atomicAdd(&g_cnt2[e], 1);
        g_tok[p] = i >> 1;
        g_pos[i] = p;
    }
    if (blockIdx.x == 0 && tid == 0) {
        int run = 0, trun = 0;
#pragma unroll
        for (int e = 0; e < NEXP; e++) {
            g_off[e] = run; g_tile_off[e] = trun;
            trun += (g_cnt[e] + 127) >> 7;
            run += g_cnt[e];
        }
        g_off[NEXP] = run; g_tile_off[NEXP] = trun;
    }
}

// ---------------- GEMM tile body (R5-proven config) ----------------------------
#define BM 128
#define BN 128
#define BK 32
#define NST 4
#define A_PITCH 80
#define B_PITCH 272
#define STG_A   (BM * A_PITCH)               // 10240
#define STG_B   (BK * B_PITCH)               // 8704
#define STG_SZ  (STG_A + STG_B)              // 18944
#define OFF_BIAS (STG_SZ * NST)              // 75776
#define OFF_SRC  (OFF_BIAS + BN * 4)         // 76288
#define SMEM_BYTES (OFF_SRC + BM * 4)        // 76800
#define EP_PITCH 272

template <int KDIM, int NCOLS, bool GATHER, bool DOGELU>
__device__ __forceinline__ void gemm_tile(
    char* smem, uint32_t sb, int tid, int wm, int wn, int g, int t,
    const uint32_t* aAddr, const uint32_t (*bAddr)[4],
    const __half* __restrict__ Abase, const __half* __restrict__ Bbase,
    const float* __restrict__ biasbase, __half* __restrict__ Cout,
    int e, int moff, int M, int rows0, int n0) {
    int*   sSrc  = (int*)(smem + OFF_SRC);
    float* sBias = (float*)(smem + OFF_BIAS);
    const __half* Bexp = Bbase + (size_t)e * KDIM * NCOLS;

    if (tid < BM) {
        int s = rows0 + tid; if (s >= M) s = M - 1;
        sSrc[tid] = GATHER ? g_tok[moff + s] : (moff + s);
    }
    if (tid < BN / 4)
        ((float4*)sBias)[tid] =
            ((const float4*)(biasbase + (size_t)e * NCOLS + n0))[tid];
    __syncthreads();

    const __half* aRow[2];
    uint32_t aDst[2];
#pragma unroll
    for (int i = 0; i < 2; i++) {
        int idx = tid + i * 256;
        int r = idx >> 2, c = idx & 3;
        aRow[i] = Abase + (size_t)sSrc[r] * KDIM + c * 8;
        aDst[i] = (uint32_t)(r * A_PITCH + c * 16);
    }
    const int kb0 = tid >> 4, nc0 = tid & 15;
    const __half* bRow0 = Bexp + (size_t)kb0 * NCOLS + n0 + nc0 * 8;
    const __half* bRow1 = Bexp + (size_t)(kb0 + 16) * NCOLS + n0 + nc0 * 8;
    const uint32_t bDst0 = (uint32_t)(STG_A + kb0 * B_PITCH + nc0 * 16);
    const uint32_t bDst1 = bDst0 + 16 * B_PITCH;

    auto fill = [&](int kc) {
        int s = kc & (NST - 1);
        uint32_t base = sb + s * STG_SZ;
        cp16(base + aDst[0], aRow[0] + kc * BK);
        cp16(base + aDst[1], aRow[1] + kc * BK);
        cp16(base + bDst0, bRow0 + (size_t)kc * BK * NCOLS);
        cp16(base + bDst1, bRow1 + (size_t)kc * BK * NCOLS);
    };

    float acc[2][8][4];
#pragma unroll
    for (int mi = 0; mi < 2; mi++)
#pragma unroll
        for (int ni = 0; ni < 8; ni++)
#pragma unroll
            for (int q = 0; q < 4; q++) acc[mi][ni][q] = 0.f;

    const int NC = KDIM / BK;
    fill(0); CP_COMMIT();
    fill(1); CP_COMMIT();
    fill(2); CP_COMMIT();

    for (int kc = 0; kc < NC; kc++) {
        int s = kc & (NST - 1);
        uint32_t base = sb + s * STG_SZ;
        CP_WAIT2();
        __syncthreads();
#pragma unroll
        for (int kk = 0; kk < 2; kk++) {
            uint32_t af[2][4], bf[8][2];
#pragma unroll
            for (int mi = 0; mi < 2; mi++)
                ldsm4(af[mi], base + aAddr[mi] + kk * 32);
#pragma unroll
            for (int p = 0; p < 4; p++) {
                uint32_t r4[4];
                ldsm4t(r4, base + bAddr[kk][p]);
                bf[2 * p][0]     = r4[0]; bf[2 * p][1]     = r4[1];
                bf[2 * p + 1][0] = r4[2]; bf[2 * p + 1][1] = r4[3];
            }
#pragma unroll
            for (int mi = 0; mi < 2; mi++)
#pragma unroll
                for (int ni = 0; ni < 8; ni++)
                    mma16816(acc[mi][ni], af[mi], bf[ni]);
        }
        if (kc + 3 < NC) fill(kc + 3);
        CP_COMMIT();
    }
    __syncthreads();

    char* ep = smem;
#pragma unroll
    for (int mi = 0; mi < 2; mi++)
#pragma unroll
        for (int ni = 0; ni < 8; ni++) {
            int col = wn * 64 + ni * 8 + 2 * t;
            float bv0 = sBias[col], bv1 = sBias[col + 1];
            int rlo = wm * 32 + mi * 16 + g;
            float v0 = acc[mi][ni][0] + bv0;
            float v1 = acc[mi][ni][1] + bv1;
            float v2 = acc[mi][ni][2] + bv0;
            float v3 = acc[mi][ni][3] + bv1;
            if (DOGELU) {
                v0 = gelu_exact(v0); v1 = gelu_exact(v1);
                v2 = gelu_exact(v2); v3 = gelu_exact(v3);
            }
            __half2 hlo = __floats2half2_rn(v0, v1);
            __half2 hhi = __floats2half2_rn(v2, v3);
            *(__half2*)(ep + rlo * EP_PITCH + col * 2) = hlo;
            *(__half2*)(ep + (rlo + 8) * EP_PITCH + col * 2) = hhi;
        }
    __syncthreads();
#pragma unroll
    for (int it = 0; it < 8; it++) {
        int id = it * 256 + tid;
        int r = id >> 4, c = id & 15;
        if (rows0 + r < M) {
            uint4 v = *(uint4*)(ep + r * EP_PITCH + c * 16);
            *(uint4*)(Cout + (size_t)(moff + rows0 + r) * NCOLS + n0 + c * 8) = v;
        }
    }
}

// ---------------- fused persistent GEMM1+GEMM2 ---------------------------------
__global__ __launch_bounds__(256, 2) void fused_gemm(
    const __half* __restrict__ xh, const __half* __restrict__ w1h,
    const float* __restrict__ b1, __half* __restrict__ hh,
    const __half* __restrict__ w2h, const float* __restrict__ b2,
    __half* __restrict__ yh) {
    extern __shared__ __align__(128) char smem[];
    __shared__ int sW;
    __shared__ int sTOF[NEXP + 1];
    const uint32_t sb = smem_u32(smem);
    const int tid  = threadIdx.x;
    const int wid  = tid >> 5, lane = tid & 31;
    const int wm = wid >> 1, wn = wid & 1;
    const int g = lane >> 2, t = lane & 3;

    if (tid <= NEXP) sTOF[tid] = g_tile_off[tid];

    const int lr = lane & 15, ls = lane >> 4;
    uint32_t aAddr[2], bAddr[2][4];
#pragma unroll
    for (int mi = 0; mi < 2; mi++)
        aAddr[mi] = (uint32_t)((wm * 32 + mi * 16 + lr) * A_PITCH + ls * 16);
#pragma unroll
    for (int kk = 0; kk < 2; kk++)
#pragma unroll
        for (int p = 0; p < 4; p++)
            bAddr[kk][p] = (uint32_t)(STG_A + (kk * 16 + lr) * B_PITCH +
                                      (wn * 8 + p * 2 + ls) * 16);

    while (true) {
        if (tid == 0) sW = atomicAdd(&g_wq[0], 1);
        __syncthreads();
        const int w = sW;
        const int tileTot = sTOF[NEXP];
        const int T1 = tileTot * NT1;
        const int T2 = tileTot * NT2;
        if (w >= T1 + T2) break;

        const bool isG1 = (w < T1);
        int gm, nt;
        if (isG1) { gm = w / NT1; nt = w % NT1; }
        else      { int w2 = w - T1; gm = w2 / NT2; nt = w2 % NT2; }
        int e = 0;
#pragma unroll
        for (int k = 1; k < NEXP; k++) if (gm >= sTOF[k]) e = k;
        const int moff  = g_off[e];
        const int M     = g_off[e + 1] - moff;
        const int rows0 = (gm - sTOF[e]) * BM;
        const int n0    = nt * BN;

        if (isG1) {
            gemm_tile<DIM, HID, true, true>(smem, sb, tid, wm, wn, g, t,
                aAddr, bAddr, xh, w1h, b1, hh, e, moff, M, rows0, n0);
            __threadfence();
            __syncthreads();
            if (tid == 0) atomicAdd(&g_dep[gm], 1);
        } else {
            if (tid == 0) {
                while (atomicAdd(&g_dep[gm], 0) < NT1) __nanosleep(200);
            }
            __syncthreads();
            gemm_tile<HID, DIM, false, false>(smem, sb, tid, wm, wn, g, t,
                aAddr, bAddr, hh, w2h, b2, yh, e, moff, M, rows0, n0);
        }
    }
}

// ---------------- combine (fp16 y) + state reset for graph replay --------------
__global__ void combine_kernel(const float* __restrict__ x, float* __restrict__ out) {
    int idx = blockIdx.x * blockDim.x + threadIdx.x;
    int n = idx >> 7;
    int c = (idx & 127) * 8;
    int p0 = g_pos[2 * n], p1 = g_pos[2 * n + 1];
    float w0 = g_top_w[2 * n], w1 = g_top_w[2 * n + 1];
    const float* xr = x + (size_t)n * DIM + c;
    float4 x0 = ((const float4*)xr)[0];
    float4 x1 = ((const float4*)xr)[1];
    uint4 ya = *(const uint4*)(g_y + (size_t)p0 * DIM + c);
    uint4 yb = *(const uint4*)(g_y + (size_t)p1 * DIM + c);
    float2 a0 = __half22float2(*(__half2*)&ya.x), a1 = __half22float2(*(__half2*)&ya.y);
    float2 a2 = __half22float2(*(__half2*)&ya.z), a3 = __half22float2(*(__half2*)&ya.w);
    float2 b0 = __half22float2(*(__half2*)&yb.x), b1 = __half22float2(*(__half2*)&yb.y);
    float2 b2 = __half22float2(*(__half2*)&yb.z), b3 = __half22float2(*(__half2*)&yb.w);
    float4 o0, o1;
    o0.x = x0.x + w0 * a0.x + w1 * b0.x;
    o0.y = x0.y + w0 * a0.y + w1 * b0.y;
    o0.z = x0.z + w0 * a1.x + w1 * b1.x;
    o0.w = x0.w + w0 * a1.y + w1 * b1.y;
    o1.x = x1.x + w0 * a2.x + w1 * b2.x;
    o1.y = x1.y + w0 * a2.y + w1 * b2.y;
    o1.z = x1.z + w0 * a3.x + w1 * b3.x;
    o1.w = x1.w + w0 * a3.y + w1 * b3.y;
    float* orow = out + (size_t)n * DIM + c;
    ((float4*)orow)[0] = o0;
    ((float4*)orow)[1] = o1;
    if (blockIdx.x == 0) {
        if (threadIdx.x < NEXP) { g_cnt[threadIdx.x] = 0; g_cnt2[threadIdx.x] = 0; }
        if (threadIdx.x < 2) g_wq[threadIdx.x] = 0;
        for (int i = threadIdx.x; i < 320; i += 256) g_dep[i] = 0;
    }
}

// ---------------- launch (single stream) ---------------------------------------
extern "C" void kernel_launch(void* const* d_in, const int* in_sizes, int n_in,
                              void* d_out, int out_size) {
    const float* x  = (const float*)d_in[0];
    const float* Wg = (const float*)d_in[1];
    const float* bg = (const float*)d_in[2];
    const float* W1 = (const float*)d_in[3];
    const float* b1 = (const float*)d_in[4];
    const float* W2 = (const float*)d_in[5];
    const float* b2 = (const float*)d_in[6];
    float* out = (float*)d_out;

    cudaFuncSetAttribute(fused_gemm,
                         cudaFuncAttributeMaxDynamicSharedMemorySize, SMEM_BYTES);

    __half *xh, *w1h, *w2h, *hh, *yh;
    cudaGetSymbolAddress((void**)&xh,  g_xh);
    cudaGetSymbolAddress((void**)&w1h, g_w1h);
    cudaGetSymbolAddress((void**)&w2h, g_w2h);
    cudaGetSymbolAddress((void**)&hh,  g_h);
    cudaGetSymbolAddress((void**)&yh,  g_y);

    prep_kernel<<<GATE_BLKS + CVT_BLKS, 256>>>(x, Wg, bg, W1, W2);     // 0
    route_kernel<<<NK / 256, 256>>>();                                  // 1
    fused_gemm<<<NPERS, 256, SMEM_BYTES>>>(xh, w1h, b1, hh,             // 2
                                           w2h, b2, yh);
    combine_kernel<<<N_TOK * 128 / 256, 256>>>(x, out);                 // 3
}